// round 1
// baseline (speedup 1.0000x reference)
#include <cuda_runtime.h>
#include <cuda_bf16.h>

#define H 1024
#define E 64
#define TM 256          // tokens per block (GEMM)
#define KC 32           // K-chunk per iteration
#define XS_STRIDE 33    // padded stride for x tile (conflict-free)
#define WS_STRIDE 65    // padded stride for w tile (conflict-free)
#define T_MAX 32768

// Scratch for logits [T, E] — static device allocation (no runtime alloc).
__device__ float g_logits[T_MAX * E];

// ---------------------------------------------------------------------------
// GEMM: logits[t][e] = sum_k x[t][k] * W[e][k]
// Grid: T/256 blocks, 256 threads. Warp w owns experts [w*8, w*8+8);
// each thread owns 8 tokens (lane + 32*i) x 8 experts -> 64 accumulators.
// ---------------------------------------------------------------------------
__global__ __launch_bounds__(256, 1)
void moe_gate_gemm(const float* __restrict__ x, const float* __restrict__ W,
                   int T) {
    __shared__ float xs[TM * XS_STRIDE];   // xs[t][k], 33.8 KB
    __shared__ float ws[KC * WS_STRIDE];   // ws[k][e],  8.3 KB

    const int tid  = threadIdx.x;
    const int lane = tid & 31;
    const int warp = tid >> 5;          // 0..7
    const int e0   = warp * 8;          // this warp's expert base
    const int t0   = blockIdx.x * TM;   // block's token base

    // x-load mapping: slot = which float4 within the 32-wide K chunk,
    // tgroup = token group; loop i gives tokens tgroup + 32*i.
    const int xslot = tid & 7;          // 0..7  (k float4 slot)
    const int xtg   = tid >> 3;         // 0..31 (token group)

    // W-load mapping: two float4s per thread cover KC x E.
    const int we0 = tid >> 3;           // expert row for f = tid       (0..31)
    const int wk0 = tid & 7;            // k-slot
    const int we1 = (tid + 256) >> 3;   // expert row for f = tid + 256 (32..63)
    const int wk1 = wk0;

    float acc[8][8];
    #pragma unroll
    for (int i = 0; i < 8; ++i)
        #pragma unroll
        for (int j = 0; j < 8; ++j) acc[i][j] = 0.f;

    float4 xr[8];
    float4 wr[2];

    // Prefetch first K chunk into registers.
    {
        const int ko = 0;
        #pragma unroll
        for (int i = 0; i < 8; ++i) {
            int t = xtg + 32 * i;
            xr[i] = *(const float4*)(x + (size_t)(t0 + t) * H + ko + xslot * 4);
        }
        wr[0] = *(const float4*)(W + (size_t)we0 * H + ko + wk0 * 4);
        wr[1] = *(const float4*)(W + (size_t)we1 * H + ko + wk1 * 4);
    }

    const int NITER = H / KC;  // 32
    for (int it = 0; it < NITER; ++it) {
        __syncthreads();   // previous compute done with smem

        // Stage registers -> shared (scalar stores, conflict-free banks)
        #pragma unroll
        for (int i = 0; i < 8; ++i) {
            int t = xtg + 32 * i;
            float* dst = &xs[t * XS_STRIDE + xslot * 4];
            dst[0] = xr[i].x; dst[1] = xr[i].y; dst[2] = xr[i].z; dst[3] = xr[i].w;
        }
        {
            float* d0 = &ws[(wk0 * 4) * WS_STRIDE + we0];
            d0[0 * WS_STRIDE] = wr[0].x; d0[1 * WS_STRIDE] = wr[0].y;
            d0[2 * WS_STRIDE] = wr[0].z; d0[3 * WS_STRIDE] = wr[0].w;
            float* d1 = &ws[(wk1 * 4) * WS_STRIDE + we1];
            d1[0 * WS_STRIDE] = wr[1].x; d1[1 * WS_STRIDE] = wr[1].y;
            d1[2 * WS_STRIDE] = wr[1].z; d1[3 * WS_STRIDE] = wr[1].w;
        }
        __syncthreads();

        // Prefetch next chunk (LDG latency hides under compute below)
        if (it + 1 < NITER) {
            const int ko = (it + 1) * KC;
            #pragma unroll
            for (int i = 0; i < 8; ++i) {
                int t = xtg + 32 * i;
                xr[i] = *(const float4*)(x + (size_t)(t0 + t) * H + ko + xslot * 4);
            }
            wr[0] = *(const float4*)(W + (size_t)we0 * H + ko + wk0 * 4);
            wr[1] = *(const float4*)(W + (size_t)we1 * H + ko + wk1 * 4);
        }

        // Compute: 32 k-steps x 64 FMAs
        #pragma unroll
        for (int kk = 0; kk < KC; ++kk) {
            float wv[8];
            #pragma unroll
            for (int j = 0; j < 8; ++j)
                wv[j] = ws[kk * WS_STRIDE + e0 + j];   // warp-broadcast
            #pragma unroll
            for (int i = 0; i < 8; ++i) {
                float xv = xs[(lane + 32 * i) * XS_STRIDE + kk];
                #pragma unroll
                for (int j = 0; j < 8; ++j)
                    acc[i][j] = fmaf(xv, wv[j], acc[i][j]);
            }
        }
    }

    // Write logits (two float4 per token row)
    #pragma unroll
    for (int i = 0; i < 8; ++i) {
        int t = t0 + lane + 32 * i;
        float* dst = &g_logits[(size_t)t * E + e0];
        float4 a = make_float4(acc[i][0], acc[i][1], acc[i][2], acc[i][3]);
        float4 b = make_float4(acc[i][4], acc[i][5], acc[i][6], acc[i][7]);
        *(float4*)(dst)     = a;
        *(float4*)(dst + 4) = b;
    }
}

// ---------------------------------------------------------------------------
// Softmax over E=64 + top-2 (jax semantics: ties -> lowest index) +
// softmax over the two top *probabilities* (exactly as reference).
// One thread per token. Output layout (f32):
//   [0 , 2T)        top_scores [T,2]
//   [2T, 4T)        top_idx    [T,2]  (cast to float)
//   [4T]            scalar 0
// ---------------------------------------------------------------------------
__global__ void moe_gate_topk(float* __restrict__ out, int T) {
    int t = blockIdx.x * blockDim.x + threadIdx.x;
    if (t >= T) return;

    const float4* p = (const float4*)(g_logits + (size_t)t * E);
    float l[E];
    #pragma unroll
    for (int i = 0; i < E / 4; ++i) {
        float4 v = p[i];
        l[4*i] = v.x; l[4*i+1] = v.y; l[4*i+2] = v.z; l[4*i+3] = v.w;
    }

    // max
    float m = l[0];
    #pragma unroll
    for (int i = 1; i < E; ++i) m = fmaxf(m, l[i]);

    // sum of exps
    float s = 0.f;
    #pragma unroll
    for (int i = 0; i < E; ++i) s += expf(l[i] - m);

    // top-1: ascending scan, strict > keeps lowest index on ties
    int i1 = 0; float v1 = l[0];
    #pragma unroll
    for (int i = 1; i < E; ++i) {
        if (l[i] > v1) { v1 = l[i]; i1 = i; }
    }
    // top-2 excluding i1
    int i2 = -1; float v2 = -3.0e38f;
    #pragma unroll
    for (int i = 0; i < E; ++i) {
        if (i != i1 && l[i] > v2) { v2 = l[i]; i2 = i; }
    }

    float inv_s = 1.f / s;
    float p1 = expf(v1 - m) * inv_s;
    float p2 = expf(v2 - m) * inv_s;

    // softmax([p1, p2]) with p1 >= p2
    float e  = expf(p2 - p1);
    float f1 = 1.f / (1.f + e);
    float f2 = e / (1.f + e);

    out[2 * t]     = f1;
    out[2 * t + 1] = f2;
    out[2 * T + 2 * t]     = (float)i1;
    out[2 * T + 2 * t + 1] = (float)i2;

    if (t == 0) out[4 * T] = 0.f;
}

extern "C" void kernel_launch(void* const* d_in, const int* in_sizes, int n_in,
                              void* d_out, int out_size) {
    const float* x = (const float*)d_in[0];   // [4, 8192, 1024] f32
    const float* W = (const float*)d_in[1];   // [64, 1024] f32
    float* out = (float*)d_out;

    const int T = in_sizes[0] / H;            // 32768

    moe_gate_gemm<<<T / TM, 256>>>(x, W, T);
    moe_gate_topk<<<(T + 127) / 128, 128>>>(out, T);
}

// round 6
// speedup vs baseline: 1.5701x; 1.5701x over previous
#include <cuda_runtime.h>
#include <cuda_bf16.h>
#include <cstdint>

#define H 1024
#define E 64
#define TPC 256          // tokens per CTA
#define KB 32            // K elements per chunk
#define NCHUNK (H / KB)  // 32

// SMEM: 3 x-planes [256 rows x 80B] + 3 w-planes [64 rows x 80B]
#define XPLANE 20480
#define WPLANE 5120
#define XS_OFF 0
#define WS_OFF (3 * XPLANE)                 // 61440
#define SMEM_TOTAL (WS_OFF + 3 * WPLANE)    // 76800
#define LSTRIDE 68                          // logits smem stride (floats)
// logits region reuses offset 0: 256*68*4 = 69632 <= 76800

__device__ __nv_bfloat16 g_w3[3 * E * H];   // pre-split W: [h|m|l][e][k]

// ---------------- helpers ----------------
__device__ __forceinline__ uint32_t smem_u32(const void* p) {
    uint32_t a;
    asm("{ .reg .u64 t; cvta.to.shared.u64 t, %1; cvt.u32.u64 %0, t; }"
        : "=r"(a) : "l"(p));
    return a;
}
__device__ __forceinline__ void ldsm4(uint32_t* r, uint32_t addr) {
    asm volatile("ldmatrix.sync.aligned.m8n8.x4.shared.b16 {%0,%1,%2,%3}, [%4];"
                 : "=r"(r[0]), "=r"(r[1]), "=r"(r[2]), "=r"(r[3]) : "r"(addr));
}
__device__ __forceinline__ void mma_bf16(float* d, const uint32_t* a, const uint32_t* b) {
    asm volatile(
        "mma.sync.aligned.m16n8k16.row.col.f32.bf16.bf16.f32 "
        "{%0,%1,%2,%3}, {%4,%5,%6,%7}, {%8,%9}, {%0,%1,%2,%3};"
        : "+f"(d[0]), "+f"(d[1]), "+f"(d[2]), "+f"(d[3])
        : "r"(a[0]), "r"(a[1]), "r"(a[2]), "r"(a[3]), "r"(b[0]), "r"(b[1]));
}
__device__ __forceinline__ void sts64(uint32_t addr, uint32_t a, uint32_t b) {
    asm volatile("st.shared.v2.b32 [%0], {%1, %2};" :: "r"(addr), "r"(a), "r"(b) : "memory");
}
__device__ __forceinline__ void sts128(uint32_t addr, uint4 v) {
    asm volatile("st.shared.v4.b32 [%0], {%1, %2, %3, %4};"
                 :: "r"(addr), "r"(v.x), "r"(v.y), "r"(v.z), "r"(v.w) : "memory");
}
// Exact split step: bf16x2 of (a,b); residuals out.
__device__ __forceinline__ uint32_t pack2(float a, float b, float& ra, float& rb) {
    __nv_bfloat16 ha = __float2bfloat16(a);
    __nv_bfloat16 hb = __float2bfloat16(b);
    ra = a - __bfloat162float(ha);
    rb = b - __bfloat162float(hb);
    return (uint32_t)__bfloat16_as_ushort(ha) | ((uint32_t)__bfloat16_as_ushort(hb) << 16);
}
__device__ __forceinline__ uint32_t pack2f(float a, float b) {
    return (uint32_t)__bfloat16_as_ushort(__float2bfloat16(a)) |
           ((uint32_t)__bfloat16_as_ushort(__float2bfloat16(b)) << 16);
}

// ---------------- W pre-split (h/m/l exact 3-way) ----------------
__global__ void convert_w_kernel(const float* __restrict__ W,
                                 float* __restrict__ out, int T) {
    int i = blockIdx.x * blockDim.x + threadIdx.x;
    if (i < E * H) {
        float v = W[i];
        __nv_bfloat16 h = __float2bfloat16(v);
        float r1 = v - __bfloat162float(h);
        __nv_bfloat16 m = __float2bfloat16(r1);
        float r2 = r1 - __bfloat162float(m);
        g_w3[i] = h;
        g_w3[E * H + i] = m;
        g_w3[2 * E * H + i] = __float2bfloat16(r2);   // exact: r2 has <= 8 sig bits
    }
    if (i == 0) out[4 * T] = 0.f;  // aux scalar output
}

// ---------------- main fused kernel (HMMA, two-bank accumulation) ----------
__global__ void __launch_bounds__(256, 1)
moe_gate_hmma(const float* __restrict__ x, float* __restrict__ out, int T) {
    extern __shared__ char smem[];
    const uint32_t sb = smem_u32(smem);
    const uint32_t XS = sb + XS_OFF, WS = sb + WS_OFF;
    float* const LS = (float*)smem;   // logits scratch (reused after mainloop)

    const int tid  = threadIdx.x;
    const int wid  = tid >> 5, lane = tid & 31;
    const int tg   = wid & 3;         // token group: rows tg*64..+63
    const int eg   = wid >> 2;        // expert group: cols eg*32..+31
    const int t0   = blockIdx.x * TPC;

    // ldmatrix lane address offsets
    const uint32_t a_lane = (uint32_t)((lane & 15) * 80 + (lane >> 4) * 16);
    const uint32_t b_lane = (uint32_t)(((lane >> 4) * 8 + (lane & 7)) * 80 +
                                       ((lane >> 3) & 1) * 16);
    const uint32_t a_base = (uint32_t)(tg * 64 * 80) + a_lane;
    const uint32_t b_base = (uint32_t)(eg * 32 * 80) + b_lane;

    // staging maps
    const int slot = tid & 7;   // x: float4 slot within 32-elem row
    const int rg   = tid >> 3;  // x: rows rg + 32*j

    // Two accumulator banks: accB for the h*h product (magnitude ~1),
    // accS for the 5 small products (hm, mh, mm, hl, lh; magnitude <= 2^-8).
    // Separating them keeps small-term rounding at small magnitude, cutting
    // total accumulation noise ~5x (the round-5 index flips).
    float accB[4][4][4], accS[4][4][4];
    #pragma unroll
    for (int i = 0; i < 4; ++i)
        #pragma unroll
        for (int j = 0; j < 4; ++j)
            #pragma unroll
            for (int k = 0; k < 4; ++k) { accB[i][j][k] = 0.f; accS[i][j][k] = 0.f; }

    float4 xr[8];
    uint4  wr[3];

#define LOAD_X(cc)                                                               \
    do {                                                                         \
        const float* xb = x + (size_t)(t0 + rg) * H + (cc) * KB + slot * 4;      \
        _Pragma("unroll") for (int j = 0; j < 8; ++j)                            \
            xr[j] = *(const float4*)(xb + (size_t)j * 32 * H);                   \
    } while (0)

#define LOAD_W(cc)                                                               \
    do {                                                                         \
        _Pragma("unroll") for (int q = 0; q < 3; ++q) {                          \
            int gi = tid + 256 * q;                                              \
            int ws = gi & 3, wrow = gi >> 2;                                     \
            wr[q] = *(const uint4*)(g_w3 + ((wrow >> 6) * (E * H) +              \
                     (wrow & 63) * H + (cc) * KB + ws * 8));                     \
        }                                                                        \
    } while (0)

    LOAD_X(0);
    LOAD_W(0);

    for (int c = 0; c < NCHUNK; ++c) {
        __syncthreads();   // previous chunk's MMAs done with smem

        // stage x: split f32 -> 3 bf16 planes (exact 3-way split)
        #pragma unroll
        for (int j = 0; j < 8; ++j) {
            int row = rg + 32 * j;
            uint32_t roff = (uint32_t)row * 80 + (uint32_t)slot * 8;
            float4 v = xr[j];
            float r1x, r1y, r1z, r1w, r2x, r2y, r2z, r2w;
            uint32_t h01 = pack2(v.x, v.y, r1x, r1y);
            uint32_t h23 = pack2(v.z, v.w, r1z, r1w);
            uint32_t m01 = pack2(r1x, r1y, r2x, r2y);
            uint32_t m23 = pack2(r1z, r1w, r2z, r2w);
            uint32_t l01 = pack2f(r2x, r2y);
            uint32_t l23 = pack2f(r2z, r2w);
            sts64(XS + roff,               h01, h23);
            sts64(XS + XPLANE + roff,      m01, m23);
            sts64(XS + 2 * XPLANE + roff,  l01, l23);
        }
        // stage W (already bf16)
        #pragma unroll
        for (int q = 0; q < 3; ++q) {
            int gi = tid + 256 * q;
            int ws = gi & 3, wrow = gi >> 2;
            int pw = wrow >> 6, e = wrow & 63;
            sts128(WS + (uint32_t)pw * WPLANE + (uint32_t)e * 80 + (uint32_t)ws * 16,
                   wr[q]);
        }
        __syncthreads();

        if (c + 1 < NCHUNK) {   // prefetch next chunk under the MMAs
            LOAD_X(c + 1);
            LOAD_W(c + 1);
        }

        // compute: 2 k-steps x 6 products x (4 tok-tiles x 4 exp-tiles)
        #pragma unroll
        for (int ks = 0; ks < 2; ++ks) {
            uint32_t bf[3][8];
            #pragma unroll
            for (int pw = 0; pw < 3; ++pw) {
                uint32_t wb = WS + (uint32_t)pw * WPLANE + b_base + (uint32_t)ks * 32;
                ldsm4(&bf[pw][0], wb);
                ldsm4(&bf[pw][4], wb + 16 * 80);
            }
            #pragma unroll
            for (int px = 0; px < 3; ++px) {
                uint32_t af[4][4];
                #pragma unroll
                for (int i = 0; i < 4; ++i)
                    ldsm4(af[i], XS + (uint32_t)px * XPLANE + a_base +
                                 (uint32_t)(i * 16 * 80) + (uint32_t)ks * 32);
                const int npw = (px == 0) ? 3 : (px == 1 ? 2 : 1);
                #pragma unroll
                for (int pw = 0; pw < 3; ++pw) {
                    if (pw < npw) {
                        const bool big = (px == 0) && (pw == 0);
                        #pragma unroll
                        for (int i = 0; i < 4; ++i)
                            #pragma unroll
                            for (int j = 0; j < 4; ++j)
                                mma_bf16(big ? accB[i][j] : accS[i][j], af[i],
                                         &bf[pw][(j >> 1) * 4 + (j & 1) * 2]);
                    }
                }
            }
        }
    }

    // ---------------- epilogue: accums -> smem logits ----------------
    __syncthreads();   // done reading XS/WS; safe to overwrite with LS
    {
        int r0 = tg * 64 + (lane >> 2);
        int c0 = eg * 32 + 2 * (lane & 3);
        #pragma unroll
        for (int i = 0; i < 4; ++i)
            #pragma unroll
            for (int j = 0; j < 4; ++j) {
                int row = r0 + i * 16;
                int col = c0 + j * 8;
                LS[row * LSTRIDE + col]           = accB[i][j][0] + accS[i][j][0];
                LS[row * LSTRIDE + col + 1]       = accB[i][j][1] + accS[i][j][1];
                LS[(row + 8) * LSTRIDE + col]     = accB[i][j][2] + accS[i][j][2];
                LS[(row + 8) * LSTRIDE + col + 1] = accB[i][j][3] + accS[i][j][3];
            }
    }
    __syncthreads();

    // ---------------- softmax + top-2, one token per thread ----------------
    {
        const int t = t0 + tid;
        float l[E];
        const float4* p = (const float4*)(LS + (size_t)tid * LSTRIDE);
        #pragma unroll
        for (int i = 0; i < E / 4; ++i) {
            float4 v = p[i];
            l[4*i] = v.x; l[4*i+1] = v.y; l[4*i+2] = v.z; l[4*i+3] = v.w;
        }

        float m = l[0];
        #pragma unroll
        for (int i = 1; i < E; ++i) m = fmaxf(m, l[i]);

        float s = 0.f;
        #pragma unroll
        for (int i = 0; i < E; ++i) s += expf(l[i] - m);

        int i1 = 0; float v1 = l[0];
        #pragma unroll
        for (int i = 1; i < E; ++i)
            if (l[i] > v1) { v1 = l[i]; i1 = i; }
        int i2 = -1; float v2 = -3.0e38f;
        #pragma unroll
        for (int i = 0; i < E; ++i)
            if (i != i1 && l[i] > v2) { v2 = l[i]; i2 = i; }

        float inv_s = 1.f / s;
        float p1 = expf(v1 - m) * inv_s;
        float p2 = expf(v2 - m) * inv_s;
        float e  = expf(p2 - p1);
        float f1 = 1.f / (1.f + e);
        float f2 = e / (1.f + e);

        out[2 * t]     = f1;
        out[2 * t + 1] = f2;
        out[2 * T + 2 * t]     = (float)i1;
        out[2 * T + 2 * t + 1] = (float)i2;
    }
}

extern "C" void kernel_launch(void* const* d_in, const int* in_sizes, int n_in,
                              void* d_out, int out_size) {
    const float* x = (const float*)d_in[0];   // [4, 8192, 1024] f32
    const float* W = (const float*)d_in[1];   // [64, 1024] f32
    float* out = (float*)d_out;
    const int T = in_sizes[0] / H;            // 32768

    cudaFuncSetAttribute(moe_gate_hmma,
                         cudaFuncAttributeMaxDynamicSharedMemorySize, SMEM_TOTAL);

    convert_w_kernel<<<(E * H + 255) / 256, 256>>>(W, out, T);
    moe_gate_hmma<<<T / TPC, 256, SMEM_TOTAL>>>(x, out, T);
}

// round 7
// speedup vs baseline: 1.9812x; 1.2618x over previous
#include <cuda_runtime.h>
#include <cuda_bf16.h>
#include <cstdint>

#define H 1024
#define E 64
#define TPC 256          // tokens per CTA
#define KB 32            // K elements per chunk
#define NCHUNK (H / KB)  // 32

// Per-buffer SMEM: 3 x-planes [256 rows x 80B] + 3 w-planes [64 rows x 80B]
#define XPLANE 20480
#define WPLANE 5120
#define WS_OFF (3 * XPLANE)          // 61440 within a buffer
#define BUFSZ  (WS_OFF + 3 * WPLANE) // 76800
#define SMEM_TOTAL (2 * BUFSZ)       // 153600 (fits 228KB, 1 CTA/SM)
#define LSTRIDE 68                   // logits smem stride (floats); 256*68*4 = 69632

__device__ __nv_bfloat16 g_w3[3 * E * H];   // pre-split W: [h|m|l][e][k]

// ---------------- helpers ----------------
__device__ __forceinline__ uint32_t smem_u32(const void* p) {
    uint32_t a;
    asm("{ .reg .u64 t; cvta.to.shared.u64 t, %1; cvt.u32.u64 %0, t; }"
        : "=r"(a) : "l"(p));
    return a;
}
__device__ __forceinline__ void ldsm4(uint32_t* r, uint32_t addr) {
    asm volatile("ldmatrix.sync.aligned.m8n8.x4.shared.b16 {%0,%1,%2,%3}, [%4];"
                 : "=r"(r[0]), "=r"(r[1]), "=r"(r[2]), "=r"(r[3]) : "r"(addr));
}
__device__ __forceinline__ void mma_bf16(float* d, const uint32_t* a, const uint32_t* b) {
    asm volatile(
        "mma.sync.aligned.m16n8k16.row.col.f32.bf16.bf16.f32 "
        "{%0,%1,%2,%3}, {%4,%5,%6,%7}, {%8,%9}, {%0,%1,%2,%3};"
        : "+f"(d[0]), "+f"(d[1]), "+f"(d[2]), "+f"(d[3])
        : "r"(a[0]), "r"(a[1]), "r"(a[2]), "r"(a[3]), "r"(b[0]), "r"(b[1]));
}
__device__ __forceinline__ void sts64(uint32_t addr, uint32_t a, uint32_t b) {
    asm volatile("st.shared.v2.b32 [%0], {%1, %2};" :: "r"(addr), "r"(a), "r"(b) : "memory");
}
__device__ __forceinline__ void sts128(uint32_t addr, uint4 v) {
    asm volatile("st.shared.v4.b32 [%0], {%1, %2, %3, %4};"
                 :: "r"(addr), "r"(v.x), "r"(v.y), "r"(v.z), "r"(v.w) : "memory");
}
// Pack (a,b) -> bf16x2 in one cvt; residuals recovered from the packed bits.
__device__ __forceinline__ uint32_t cvt2(float a, float b) {
    uint32_t r;
    asm("cvt.rn.bf16x2.f32 %0, %1, %2;" : "=r"(r) : "f"(b), "f"(a));
    return r;  // a in low 16, b in high 16
}
__device__ __forceinline__ uint32_t pack2(float a, float b, float& ra, float& rb) {
    uint32_t r = cvt2(a, b);
    ra = a - __uint_as_float(r << 16);
    rb = b - __uint_as_float(r & 0xFFFF0000u);
    return r;
}

// ---------------- W pre-split (h/m/l exact 3-way) ----------------
__global__ void convert_w_kernel(const float* __restrict__ W,
                                 float* __restrict__ out, int T) {
    int i = blockIdx.x * blockDim.x + threadIdx.x;
    if (i < E * H) {
        float v = W[i];
        __nv_bfloat16 h = __float2bfloat16(v);
        float r1 = v - __bfloat162float(h);
        __nv_bfloat16 m = __float2bfloat16(r1);
        float r2 = r1 - __bfloat162float(m);
        g_w3[i] = h;
        g_w3[E * H + i] = m;
        g_w3[2 * E * H + i] = __float2bfloat16(r2);   // exact: r2 has <= 8 sig bits
    }
    if (i == 0) out[4 * T] = 0.f;  // aux scalar output
}

// ---------------- main fused kernel (HMMA, double-buffered) ----------------
__global__ void __launch_bounds__(256, 1)
moe_gate_hmma(const float* __restrict__ x, float* __restrict__ out, int T) {
    extern __shared__ char smem[];
    const uint32_t sb = smem_u32(smem);
    float* const LS = (float*)smem;   // logits scratch (reused after mainloop)

    const int tid  = threadIdx.x;
    const int wid  = tid >> 5, lane = tid & 31;
    const int tg   = wid & 3;         // token group: rows tg*64..+63
    const int eg   = wid >> 2;        // expert group: cols eg*32..+31
    const int t0   = blockIdx.x * TPC;

    // ldmatrix lane address offsets
    const uint32_t a_lane = (uint32_t)((lane & 15) * 80 + (lane >> 4) * 16);
    const uint32_t b_lane = (uint32_t)(((lane >> 4) * 8 + (lane & 7)) * 80 +
                                       ((lane >> 3) & 1) * 16);
    const uint32_t a_base = (uint32_t)(tg * 64 * 80) + a_lane;
    const uint32_t b_base = (uint32_t)(eg * 32 * 80) + b_lane;

    // staging maps
    const int slot = tid & 7;   // x: float4 slot within 32-elem row
    const int rg   = tid >> 3;  // x: rows rg + 32*j

    // Two accumulator banks: accB for h*h (magnitude ~1), accS for the 5
    // small products (hm, mh, mm, hl, lh) — keeps small-term rounding at
    // small magnitude (round-5 fix, validated).
    float accB[4][4][4], accS[4][4][4];
    #pragma unroll
    for (int i = 0; i < 4; ++i)
        #pragma unroll
        for (int j = 0; j < 4; ++j)
            #pragma unroll
            for (int k = 0; k < 4; ++k) { accB[i][j][k] = 0.f; accS[i][j][k] = 0.f; }

    float4 xr[8];
    uint4  wr[3];

#define LOAD_X(cc)                                                               \
    do {                                                                         \
        const float* xb = x + (size_t)(t0 + rg) * H + (cc) * KB + slot * 4;      \
        _Pragma("unroll") for (int j = 0; j < 8; ++j)                            \
            xr[j] = *(const float4*)(xb + (size_t)j * 32 * H);                   \
    } while (0)

#define LOAD_W(cc)                                                               \
    do {                                                                         \
        _Pragma("unroll") for (int q = 0; q < 3; ++q) {                          \
            int gi = tid + 256 * q;                                              \
            int ws = gi & 3, wrow = gi >> 2;                                     \
            wr[q] = *(const uint4*)(g_w3 + ((wrow >> 6) * (E * H) +              \
                     (wrow & 63) * H + (cc) * KB + ws * 8));                     \
        }                                                                        \
    } while (0)

// Stage xr/wr into buffer at base bb (split x into 3 bf16 planes).
#define STAGE(bb)                                                                \
    do {                                                                         \
        const uint32_t XSb = (bb), WSb = (bb) + WS_OFF;                          \
        _Pragma("unroll") for (int j = 0; j < 8; ++j) {                          \
            int row = rg + 32 * j;                                               \
            uint32_t roff = (uint32_t)row * 80 + (uint32_t)slot * 8;             \
            float4 v = xr[j];                                                    \
            float r1x, r1y, r1z, r1w, r2x, r2y, r2z, r2w;                        \
            uint32_t h01 = pack2(v.x, v.y, r1x, r1y);                            \
            uint32_t h23 = pack2(v.z, v.w, r1z, r1w);                            \
            uint32_t m01 = pack2(r1x, r1y, r2x, r2y);                            \
            uint32_t m23 = pack2(r1z, r1w, r2z, r2w);                            \
            uint32_t l01 = cvt2(r2x, r2y);                                       \
            uint32_t l23 = cvt2(r2z, r2w);                                       \
            sts64(XSb + roff,              h01, h23);                            \
            sts64(XSb + XPLANE + roff,     m01, m23);                            \
            sts64(XSb + 2 * XPLANE + roff, l01, l23);                            \
        }                                                                        \
        _Pragma("unroll") for (int q = 0; q < 3; ++q) {                          \
            int gi = tid + 256 * q;                                              \
            int ws = gi & 3, wrow = gi >> 2;                                     \
            int pw = wrow >> 6, e = wrow & 63;                                   \
            sts128(WSb + (uint32_t)pw * WPLANE + (uint32_t)e * 80 +              \
                   (uint32_t)ws * 16, wr[q]);                                    \
        }                                                                        \
    } while (0)

    // prologue: stage chunk 0 into buffer 0
    LOAD_X(0);
    LOAD_W(0);
    STAGE(sb);
    __syncthreads();

    for (int c = 0; c < NCHUNK; ++c) {
        const uint32_t cbuf = sb + (uint32_t)(c & 1) * BUFSZ;
        const uint32_t nbuf = sb + (uint32_t)((c + 1) & 1) * BUFSZ;

        if (c + 1 < NCHUNK) {   // get next chunk's LDGs in flight first
            LOAD_X(c + 1);
            LOAD_W(c + 1);
        }

        // compute chunk c from cbuf: 2 k-steps x 6 products x 16 tiles
        const uint32_t XSc = cbuf, WSc = cbuf + WS_OFF;
        #pragma unroll
        for (int ks = 0; ks < 2; ++ks) {
            uint32_t bf[3][8];
            #pragma unroll
            for (int pw = 0; pw < 3; ++pw) {
                uint32_t wb = WSc + (uint32_t)pw * WPLANE + b_base + (uint32_t)ks * 32;
                ldsm4(&bf[pw][0], wb);
                ldsm4(&bf[pw][4], wb + 16 * 80);
            }
            #pragma unroll
            for (int px = 0; px < 3; ++px) {
                uint32_t af[4][4];
                #pragma unroll
                for (int i = 0; i < 4; ++i)
                    ldsm4(af[i], XSc + (uint32_t)px * XPLANE + a_base +
                                 (uint32_t)(i * 16 * 80) + (uint32_t)ks * 32);
                const int npw = (px == 0) ? 3 : (px == 1 ? 2 : 1);
                #pragma unroll
                for (int pw = 0; pw < 3; ++pw) {
                    if (pw < npw) {
                        const bool big = (px == 0) && (pw == 0);
                        #pragma unroll
                        for (int i = 0; i < 4; ++i)
                            #pragma unroll
                            for (int j = 0; j < 4; ++j)
                                mma_bf16(big ? accB[i][j] : accS[i][j], af[i],
                                         &bf[pw][(j >> 1) * 4 + (j & 1) * 2]);
                    }
                }
            }
        }

        // stage chunk c+1 into the other buffer (overlaps MMA drain)
        if (c + 1 < NCHUNK) STAGE(nbuf);

        __syncthreads();
    }

    // ---------------- epilogue: accums -> smem logits ----------------
    {
        int r0 = tg * 64 + (lane >> 2);
        int c0 = eg * 32 + 2 * (lane & 3);
        #pragma unroll
        for (int i = 0; i < 4; ++i)
            #pragma unroll
            for (int j = 0; j < 4; ++j) {
                int row = r0 + i * 16;
                int col = c0 + j * 8;
                LS[row * LSTRIDE + col]           = accB[i][j][0] + accS[i][j][0];
                LS[row * LSTRIDE + col + 1]       = accB[i][j][1] + accS[i][j][1];
                LS[(row + 8) * LSTRIDE + col]     = accB[i][j][2] + accS[i][j][2];
                LS[(row + 8) * LSTRIDE + col + 1] = accB[i][j][3] + accS[i][j][3];
            }
    }
    __syncthreads();

    // ---------------- softmax + top-2, one token per thread ----------------
    {
        const int t = t0 + tid;
        float l[E];
        const float4* p = (const float4*)(LS + (size_t)tid * LSTRIDE);
        #pragma unroll
        for (int i = 0; i < E / 4; ++i) {
            float4 v = p[i];
            l[4*i] = v.x; l[4*i+1] = v.y; l[4*i+2] = v.z; l[4*i+3] = v.w;
        }

        float m = l[0];
        #pragma unroll
        for (int i = 1; i < E; ++i) m = fmaxf(m, l[i]);

        float s = 0.f;
        #pragma unroll
        for (int i = 0; i < E; ++i) s += expf(l[i] - m);

        int i1 = 0; float v1 = l[0];
        #pragma unroll
        for (int i = 1; i < E; ++i)
            if (l[i] > v1) { v1 = l[i]; i1 = i; }
        int i2 = -1; float v2 = -3.0e38f;
        #pragma unroll
        for (int i = 0; i < E; ++i)
            if (i != i1 && l[i] > v2) { v2 = l[i]; i2 = i; }

        float inv_s = 1.f / s;
        float p1 = expf(v1 - m) * inv_s;
        float p2 = expf(v2 - m) * inv_s;
        float e  = expf(p2 - p1);
        float f1 = 1.f / (1.f + e);
        float f2 = e / (1.f + e);

        out[2 * t]     = f1;
        out[2 * t + 1] = f2;
        out[2 * T + 2 * t]     = (float)i1;
        out[2 * T + 2 * t + 1] = (float)i2;
    }
}

extern "C" void kernel_launch(void* const* d_in, const int* in_sizes, int n_in,
                              void* d_out, int out_size) {
    const float* x = (const float*)d_in[0];   // [4, 8192, 1024] f32
    const float* W = (const float*)d_in[1];   // [64, 1024] f32
    float* out = (float*)d_out;
    const int T = in_sizes[0] / H;            // 32768

    cudaFuncSetAttribute(moe_gate_hmma,
                         cudaFuncAttributeMaxDynamicSharedMemorySize, SMEM_TOTAL);

    convert_w_kernel<<<(E * H + 255) / 256, 256>>>(W, out, T);
    moe_gate_hmma<<<T / TPC, 256, SMEM_TOTAL>>>(x, out, T);
}